// round 17
// baseline (speedup 1.0000x reference)
#include <cuda_runtime.h>
#include <cuda_fp16.h>
#include <cstdint>
#include <cmath>

#define DIMX 768
#define NHEAD 12
#define HD 64
#define BATCH 4
#define SEQ 2048
#define ROWS_TOT (BATCH*SEQ)   /* 8192 */
#define BHT (BATCH*NHEAD)
#define Q_SCALE (0.125f * 1.4426950408889634f)

// ---- scratch (allocation-free __device__ globals; device-side access ONLY) ----
__device__ __align__(16) __half g_xh[ROWS_TOT*DIMX];
__device__ __align__(16) __half g_w1h[3*DIMX*DIMX];
__device__ __align__(16) __half g_w2h[DIMX*DIMX];
__device__ __align__(16) __half g_q[BHT*SEQ*HD];        // fp16, pre-scaled (log2e folded)
__device__ __align__(16) __half g_k[BHT*SEQ*HD];
__device__ __align__(16) __half g_vt[BHT*HD*SEQ];       // V transposed, fp16
__device__ __align__(16) __half g_att[ROWS_TOT*DIMX];

#define MMA_F16(d0,d1,d2,d3,a0,a1,a2,a3,b0,b1)                               \
  asm volatile("mma.sync.aligned.m16n8k16.row.col.f32.f16.f16.f32 "          \
               "{%0,%1,%2,%3}, {%4,%5,%6,%7}, {%8,%9}, {%0,%1,%2,%3};\n"     \
               : "+f"(d0), "+f"(d1), "+f"(d2), "+f"(d3)                      \
               : "r"(a0), "r"(a1), "r"(a2), "r"(a3), "r"(b0), "r"(b1))

#define LDSM4(r0,r1,r2,r3, addr)                                             \
  asm volatile("ldmatrix.sync.aligned.m8n8.x4.shared.b16 {%0,%1,%2,%3}, [%4];\n" \
               : "=r"(r0), "=r"(r1), "=r"(r2), "=r"(r3) : "r"(addr))

#define CP16(d, s)                                                            \
  asm volatile("cp.async.cg.shared.global [%0], [%1], 16;\n"                  \
               :: "r"(d), "l"(s))
#define CPCOMMIT asm volatile("cp.async.commit_group;\n")

// ============================================================
// fp32 -> fp16 convert. WHICH: 0->x 1->qkv_w 2->proj_w
// ============================================================
template<int WHICH>
__global__ void cvt_f16(const float4* __restrict__ src, int n4)
{
    __half2* dst = (WHICH == 0) ? (__half2*)g_xh
                 : (WHICH == 1) ? (__half2*)g_w1h
                                : (__half2*)g_w2h;
    int i = blockIdx.x*blockDim.x + threadIdx.x;
    if (i >= n4) return;
    float4 v = src[i];
    dst[i*2]   = __floats2half2_rn(v.x, v.y);
    dst[i*2+1] = __floats2half2_rn(v.z, v.w);
}

// ============================================================
// fp16 GEMM (fp32 accum): BM=64 BN=128 BK=32, 256 thr,
// 3 CTAs/SM, 3-stage cp.async, ldmatrix.x4.
// Warp grid: 2(m) x 4(n), warp tile 32x32.
// ============================================================
#define SH 40                          /* smem row stride (halves) */
#define GA_B (64*SH*2)                 /* A array: 5120 B   */
#define GB_B (128*SH*2)                /* B array: 10240 B  */
#define GSTG_B (GA_B+GB_B)             /* 15360 B per stage */
#define GH_SMEM (3*GSTG_B)             /* 46080 B           */
#define NKT (DIMX/32)                  /* 24 k-tiles        */

template<bool QKV>
__global__ __launch_bounds__(256, 3) void gemm_f16(const float* __restrict__ bias,
                                                   float* __restrict__ out)
{
    const __half* __restrict__ A = QKV ? g_xh  : g_att;
    const __half* __restrict__ B = QKV ? g_w1h : g_w2h;

    extern __shared__ __half smg[];
    const unsigned smem_u32 = (unsigned)__cvta_generic_to_shared(smg);

    const int tid  = threadIdx.x;
    const int lane = tid & 31;
    const int w    = tid >> 5;
    const int g    = lane >> 2;
    const int tig  = lane & 3;
    const int wm   = w & 1;          // 2 warp rows (32 each)
    const int wn   = w >> 1;         // 4 warp cols (32 each)
    const int bm   = blockIdx.y * 64;
    const int bn   = blockIdx.x * 128;

    const unsigned aoff = (unsigned)(((lane & 15)*SH + ((lane >> 4) << 3)) * 2);

    float acc[2][4][4];
    #pragma unroll
    for (int i = 0; i < 2; i++)
        #pragma unroll
        for (int j = 0; j < 4; j++)
            #pragma unroll
            for (int r = 0; r < 4; r++) acc[i][j][r] = 0.f;

    auto load_stage = [&](int st, int k0) {
        unsigned base = smem_u32 + (unsigned)st*GSTG_B;
        // A: 64 rows x 32 halves = 256 chunks (1/thread)
        {
            int row = tid >> 2;
            int c8  = (tid & 3) * 8;
            CP16(base + (unsigned)(row*SH + c8)*2u,
                 &A[(size_t)(bm+row)*DIMX + k0 + c8]);
        }
        // B: 128 rows x 32 halves = 512 chunks (2/thread)
        #pragma unroll
        for (int t = 0; t < 2; t++) {
            int idx = tid + t*256;
            int row = idx >> 2;
            int c8  = (idx & 3) * 8;
            CP16(base + GA_B + (unsigned)(row*SH + c8)*2u,
                 &B[(size_t)(bn+row)*DIMX + k0 + c8]);
        }
    };

    load_stage(0, 0);  CPCOMMIT;
    load_stage(1, 32); CPCOMMIT;

    for (int kt = 0; kt < NKT; kt++) {
        const int s = kt % 3;
        if (kt >= NKT-2) asm volatile("cp.async.wait_group 0;\n");
        else             asm volatile("cp.async.wait_group 1;\n");
        __syncthreads();

        if (kt + 2 < NKT) {
            load_stage((kt+2) % 3, (kt+2)*32);
            CPCOMMIT;
        }

        const unsigned sA = smem_u32 + s*GSTG_B;
        const unsigned sB = sA + GA_B;

        #pragma unroll
        for (int ks = 0; ks < 32; ks += 16) {
            unsigned af[2][4];
            #pragma unroll
            for (int mf = 0; mf < 2; mf++) {
                unsigned ra = sA + (unsigned)(((wm*32 + mf*16)*SH + ks)*2) + aoff;
                LDSM4(af[mf][0], af[mf][1], af[mf][2], af[mf][3], ra);
            }
            unsigned bf[4][2];
            #pragma unroll
            for (int p = 0; p < 2; p++) {
                unsigned rb = sB + (unsigned)(((wn*32 + p*16)*SH + ks)*2) + aoff;
                unsigned r0, r1, r2, r3;
                LDSM4(r0, r1, r2, r3, rb);
                bf[p*2][0] = r0; bf[p*2+1][0] = r1;
                bf[p*2][1] = r2; bf[p*2+1][1] = r3;
            }
            #pragma unroll
            for (int nf = 0; nf < 4; nf++)
                #pragma unroll
                for (int mf = 0; mf < 2; mf++)
                    MMA_F16(acc[mf][nf][0], acc[mf][nf][1],
                            acc[mf][nf][2], acc[mf][nf][3],
                            af[mf][0], af[mf][1], af[mf][2], af[mf][3],
                            bf[nf][0], bf[nf][1]);
        }
    }

    // ---- epilogue ----
    #pragma unroll
    for (int nf = 0; nf < 4; nf++) {
        int col = bn + wn*32 + nf*8 + tig*2;
        float bx = bias[col], by = bias[col+1];
        if (QKV) {
            int c  = col / DIMX;            // 0=Q 1=K 2=V (uniform per CTA)
            int hh = (col % DIMX) >> 6;
            int dd = col & 63;
            #pragma unroll
            for (int mf = 0; mf < 2; mf++)
                #pragma unroll
                for (int h2 = 0; h2 < 2; h2++) {
                    int row = bm + wm*32 + mf*16 + g + h2*8;
                    int b_ = row >> 11, n_ = row & 2047;
                    float vx = acc[mf][nf][h2*2+0] + bx;
                    float vy = acc[mf][nf][h2*2+1] + by;
                    if (c == 0) {
                        size_t idx = (((size_t)(b_*NHEAD + hh))*SEQ + n_)*HD + dd;
                        *(__half2*)&g_q[idx] =
                            __floats2half2_rn(vx*Q_SCALE, vy*Q_SCALE);
                    } else if (c == 1) {
                        size_t idx = (((size_t)(b_*NHEAD + hh))*SEQ + n_)*HD + dd;
                        *(__half2*)&g_k[idx] = __floats2half2_rn(vx, vy);
                    } else {
                        size_t idx = (((size_t)(b_*NHEAD + hh))*HD + dd)*SEQ + n_;
                        g_vt[idx]     = __float2half_rn(vx);
                        g_vt[idx+SEQ] = __float2half_rn(vy);
                    }
                }
        } else {
            #pragma unroll
            for (int mf = 0; mf < 2; mf++)
                #pragma unroll
                for (int h2 = 0; h2 < 2; h2++) {
                    int row = bm + wm*32 + mf*16 + g + h2*8;
                    float2 v = make_float2(acc[mf][nf][h2*2+0] + bx,
                                           acc[mf][nf][h2*2+1] + by);
                    *(float2*)&out[(size_t)row*DIMX + col] = v;
                }
        }
    }
}

// ============================================================
// Flash attention: 128-kv K/V tiles (2-stage), two 64-kv chunks,
// QK^T fp16 (log2 units), h2exp2, l via ones-row MMA,
// rescale skipped when the running max is unchanged (warp-uniform).
// 2 CTAs/SM. Block = (b*h, 128 q rows).
// ============================================================
#define KH_STRIDE 72                        /* halves per K row (kv rows) */
#define VT_STRIDE 136                       /* halves per Vt row (d rows) */
#define K_BYTES   (128*KH_STRIDE*2)         /* 18432 */
#define V_ROWS    80
#define V_BYTES   (V_ROWS*VT_STRIDE*2)      /* 21760 */
#define AT_STG    (K_BYTES + V_BYTES)       /* 40192 per stage */
#define AT_SMEM   (2*AT_STG)                /* 80384 */
#define NTILES    (SEQ/128)                 /* 16 */

__global__ __launch_bounds__(256, 2) void attn_mma()
{
    extern __shared__ char sma[];
    const unsigned smem_u32 = (unsigned)__cvta_generic_to_shared(sma);

    const int tid  = threadIdx.x;
    const int lane = tid & 31;
    const int w    = tid >> 5;
    const int g    = lane >> 2;
    const int tig  = lane & 3;
    const int bh   = blockIdx.y;
    const int q0   = blockIdx.x * 128;
    const size_t kbase = (size_t)bh * SEQ * HD;
    const size_t vbase = (size_t)bh * HD * SEQ;
    const int row0 = q0 + w*16 + g;

    const unsigned koff = (unsigned)(((lane & 15)*KH_STRIDE + ((lane >> 4) << 3)) * 2);
    const unsigned voff = (unsigned)(((lane & 15)*VT_STRIDE + ((lane >> 4) << 3)) * 2);

    // init ones/zero rows (64..79) of both V stages
    {
        __half* vs = (__half*)sma;
        for (int idx = tid; idx < 2*16*VT_STRIDE; idx += 256) {
            int st  = idx / (16*VT_STRIDE);
            int rem = idx % (16*VT_STRIDE);
            int r   = rem / VT_STRIDE;
            int c   = rem % VT_STRIDE;
            vs[(st*AT_STG + K_BYTES)/2 + (64 + r)*VT_STRIDE + c] =
                (r == 0) ? __float2half(1.0f) : __float2half(0.0f);
        }
    }

    // Q fragments
    unsigned qf[4][4];
    #pragma unroll
    for (int ks = 0; ks < 4; ks++) {
        int c0 = ks*16 + tig*2;
        qf[ks][0] = *(const unsigned*)&g_q[kbase + (size_t) row0   *HD + c0    ];
        qf[ks][1] = *(const unsigned*)&g_q[kbase + (size_t)(row0+8)*HD + c0    ];
        qf[ks][2] = *(const unsigned*)&g_q[kbase + (size_t) row0   *HD + c0 + 8];
        qf[ks][3] = *(const unsigned*)&g_q[kbase + (size_t)(row0+8)*HD + c0 + 8];
    }

    float m0 = -INFINITY, m1 = -INFINITY;
    float o[8][4], ol[4];
    #pragma unroll
    for (int nf = 0; nf < 8; nf++)
        #pragma unroll
        for (int r = 0; r < 4; r++) o[nf][r] = 0.f;
    #pragma unroll
    for (int r = 0; r < 4; r++) ol[r] = 0.f;

    auto load_tile = [&](int st, int j0) {
        unsigned sb = smem_u32 + (unsigned)st*AT_STG;
        #pragma unroll
        for (int t = 0; t < 4; t++) {
            int idx = tid + t*256;
            int row = idx >> 3;
            int c8  = (idx & 7) * 8;
            CP16(sb + (unsigned)(row*KH_STRIDE + c8)*2u,
                 &g_k[kbase + (size_t)(j0+row)*HD + c8]);
        }
        unsigned vb = sb + K_BYTES;
        #pragma unroll
        for (int t = 0; t < 4; t++) {
            int idx = tid + t*256;
            int d   = idx >> 4;
            int c8  = (idx & 15) * 8;
            CP16(vb + (unsigned)(d*VT_STRIDE + c8)*2u,
                 &g_vt[vbase + (size_t)d*SEQ + j0 + c8]);
        }
    };

    load_tile(0, 0); CPCOMMIT;

    for (int it = 0; it < NTILES; it++) {
        const int s = it & 1;
        asm volatile("cp.async.wait_group 0;\n");
        __syncthreads();

        if (it + 1 < NTILES) {
            load_tile(s^1, (it+1)*128);
            CPCOMMIT;
        }

        const unsigned sK = smem_u32 + (unsigned)s*AT_STG;
        const unsigned sV = sK + K_BYTES;

        #pragma unroll
        for (int ch = 0; ch < 2; ch++) {
            // ---- S = Q K^T (log2 units) ----
            float sres[8][4];
            #pragma unroll
            for (int nf = 0; nf < 8; nf++)
                #pragma unroll
                for (int r = 0; r < 4; r++) sres[nf][r] = 0.f;

            #pragma unroll
            for (int ks = 0; ks < 4; ks++) {
                #pragma unroll
                for (int p = 0; p < 4; p++) {
                    unsigned rb = sK + (unsigned)(((ch*64 + p*16)*KH_STRIDE + ks*16)*2) + koff;
                    unsigned r0, r1, r2, r3;
                    LDSM4(r0, r1, r2, r3, rb);
                    MMA_F16(sres[2*p][0], sres[2*p][1], sres[2*p][2], sres[2*p][3],
                            qf[ks][0], qf[ks][1], qf[ks][2], qf[ks][3], r0, r2);
                    MMA_F16(sres[2*p+1][0], sres[2*p+1][1], sres[2*p+1][2], sres[2*p+1][3],
                            qf[ks][0], qf[ks][1], qf[ks][2], qf[ks][3], r1, r3);
                }
            }

            // ---- max reduce ----
            float rm0 = -INFINITY, rm1 = -INFINITY;
            #pragma unroll
            for (int nf = 0; nf < 8; nf++) {
                rm0 = fmaxf(rm0, fmaxf(sres[nf][0], sres[nf][1]));
                rm1 = fmaxf(rm1, fmaxf(sres[nf][2], sres[nf][3]));
            }
            rm0 = fmaxf(rm0, __shfl_xor_sync(0xFFFFFFFFu, rm0, 1));
            rm0 = fmaxf(rm0, __shfl_xor_sync(0xFFFFFFFFu, rm0, 2));
            rm1 = fmaxf(rm1, __shfl_xor_sync(0xFFFFFFFFu, rm1, 1));
            rm1 = fmaxf(rm1, __shfl_xor_sync(0xFFFFFFFFu, rm1, 2));
            float mn0 = fmaxf(m0, rm0), mn1 = fmaxf(m1, rm1);
            float al0 = exp2f(m0 - mn0), al1 = exp2f(m1 - mn1);
            m0 = mn0; m1 = mn1;

            // rescale only if some row's max changed (warp-uniform branch)
            if (!__all_sync(0xFFFFFFFFu, (al0 == 1.0f) && (al1 == 1.0f))) {
                #pragma unroll
                for (int nf = 0; nf < 8; nf++) {
                    o[nf][0] *= al0; o[nf][1] *= al0;
                    o[nf][2] *= al1; o[nf][3] *= al1;
                }
                ol[0] *= al0; ol[1] *= al0;
                ol[2] *= al1; ol[3] *= al1;
            }

            // ---- P = exp2(S-m) fp16; O += P@V; l += P@1 ----
            #pragma unroll
            for (int jj = 0; jj < 4; jj++) {
                __half2 ph[4];
                ph[0] = h2exp2(__floats2half2_rn(sres[2*jj  ][0]-mn0, sres[2*jj  ][1]-mn0));
                ph[1] = h2exp2(__floats2half2_rn(sres[2*jj  ][2]-mn1, sres[2*jj  ][3]-mn1));
                ph[2] = h2exp2(__floats2half2_rn(sres[2*jj+1][0]-mn0, sres[2*jj+1][1]-mn0));
                ph[3] = h2exp2(__floats2half2_rn(sres[2*jj+1][2]-mn1, sres[2*jj+1][3]-mn1));
                unsigned pa0 = *reinterpret_cast<unsigned*>(&ph[0]);
                unsigned pa1 = *reinterpret_cast<unsigned*>(&ph[1]);
                unsigned pa2 = *reinterpret_cast<unsigned*>(&ph[2]);
                unsigned pa3 = *reinterpret_cast<unsigned*>(&ph[3]);
                const int kc = ch*64 + jj*16;
                #pragma unroll
                for (int p = 0; p < 4; p++) {
                    unsigned rb = sV + (unsigned)((p*16*VT_STRIDE + kc)*2) + voff;
                    unsigned r0, r1, r2, r3;
                    LDSM4(r0, r1, r2, r3, rb);
                    MMA_F16(o[2*p][0], o[2*p][1], o[2*p][2], o[2*p][3],
                            pa0, pa1, pa2, pa3, r0, r2);
                    MMA_F16(o[2*p+1][0], o[2*p+1][1], o[2*p+1][2], o[2*p+1][3],
                            pa0, pa1, pa2, pa3, r1, r3);
                }
                {
                    unsigned rb = sV + (unsigned)((64*VT_STRIDE + kc)*2) + voff;
                    unsigned r0, r1, r2, r3;
                    LDSM4(r0, r1, r2, r3, rb);
                    MMA_F16(ol[0], ol[1], ol[2], ol[3], pa0, pa1, pa2, pa3, r0, r2);
                }
            }
        }
    }

    // ---- epilogue ----
    int src = lane & 28;
    float lw0 = __shfl_sync(0xFFFFFFFFu, ol[0], src);
    float lw1 = __shfl_sync(0xFFFFFFFFu, ol[2], src);
    float inv0 = 1.0f / lw0, inv1 = 1.0f / lw1;
    int b_ = bh / NHEAD, hh = bh % NHEAD;
    #pragma unroll
    for (int nf = 0; nf < 8; nf++) {
        int col = hh*64 + nf*8 + tig*2;
        *(__half2*)&g_att[((size_t)(b_*SEQ + row0  ))*DIMX + col] =
            __floats2half2_rn(o[nf][0]*inv0, o[nf][1]*inv0);
        *(__half2*)&g_att[((size_t)(b_*SEQ + row0+8))*DIMX + col] =
            __floats2half2_rn(o[nf][2]*inv1, o[nf][3]*inv1);
    }
}

// ============================================================
extern "C" void kernel_launch(void* const* d_in, const int* in_sizes, int n_in,
                              void* d_out, int out_size)
{
    const float* x      = (const float*)d_in[0];
    const float* qkv_w  = (const float*)d_in[1];
    const float* qkv_b  = (const float*)d_in[2];
    const float* proj_w = (const float*)d_in[3];
    const float* proj_b = (const float*)d_in[4];
    float* out = (float*)d_out;
    (void)in_sizes; (void)n_in; (void)out_size;

    cudaFuncSetAttribute(gemm_f16<true>,
                         cudaFuncAttributeMaxDynamicSharedMemorySize, GH_SMEM);
    cudaFuncSetAttribute(gemm_f16<false>,
                         cudaFuncAttributeMaxDynamicSharedMemorySize, GH_SMEM);
    cudaFuncSetAttribute(attn_mma,
                         cudaFuncAttributeMaxDynamicSharedMemorySize, AT_SMEM);

    {
        int n4 = ROWS_TOT*DIMX/4;
        cvt_f16<0><<<(n4+255)/256, 256>>>((const float4*)x, n4);
        n4 = 3*DIMX*DIMX/4;
        cvt_f16<1><<<(n4+255)/256, 256>>>((const float4*)qkv_w, n4);
        n4 = DIMX*DIMX/4;
        cvt_f16<2><<<(n4+255)/256, 256>>>((const float4*)proj_w, n4);
    }

    dim3 g1(2304/128, ROWS_TOT/64);    // (18, 128)
    gemm_f16<true><<<g1, 256, GH_SMEM>>>(qkv_b, nullptr);

    dim3 g2(SEQ/128, BATCH*NHEAD);     // (16, 48)
    attn_mma<<<g2, 256, AT_SMEM>>>();

    dim3 g3(DIMX/128, ROWS_TOT/64);    // (6, 128)
    gemm_f16<false><<<g3, 256, GH_SMEM>>>(proj_b, out);
}